// round 15
// baseline (speedup 1.0000x reference)
#include <cuda_runtime.h>
#include <cuda_bf16.h>
#include <cstdint>
#include <math.h>

#define NN 2048
#define EE 65536
#define HH 8
#define CC 128
#define NEG 0.2f
#define BK 8
#define DCAP 128          // per-dst bucket capacity (mean deg 32, 17 sigma headroom)

// ---------------- device scratch ----------------
__device__ float          g_A  [NN*NN];    // fp32 raw adjacency counts (NO diag)
__device__ float          g_A2f[NN*NN];    // fp32 A^2 raw (path counts)
__device__ float          g_R  [NN*NN];    // fp32 mask accumulator
__device__ __nv_bfloat16  g_A2bf[NN*NN];   // bf16 A'^2
__device__ __nv_bfloat16  g_STbf[NN*NN];   // (A' + A'^2)^T in bf16
__device__ float g_xh[NN*HH*CC];
__device__ float g_si[NN*HH];
__device__ float g_sj[NN*HH];
__device__ float g_z [EE*HH];              // layout: [e][h]
__device__ float g_mv[EE];
__device__ unsigned g_hmaxu[2][HH];        // encoded per-head maxima, per layer
__device__ float    g_Zsum [2][HH];        // per-head exp sums, per layer
__device__ float g_norm2[NN];
__device__ int   g_cur[NN];                // per-dst in-degree (bucket fill)
__device__ int   g_ssrc[NN*DCAP];
__device__ int   g_seid[NN*DCAP];
__device__ float g_h1[NN*CC];
__device__ float g_xskip[NN*CC];
__device__ int   g_is64;

__device__ __forceinline__ int eidx(const void* ei, int pos) {
    if (g_is64) return (int)((const long long*)ei)[pos];
    return ((const int*)ei)[pos];
}

// monotone float<->uint encoding for atomicMax over floats
__device__ __forceinline__ unsigned encf(float f) {
    unsigned b = __float_as_uint(f);
    return (b & 0x80000000u) ? ~b : (b | 0x80000000u);
}
__device__ __forceinline__ float decf(unsigned u) {
    unsigned b = (u & 0x80000000u) ? (u ^ 0x80000000u) : ~u;
    return __uint_as_float(b);
}

// ---------------- zeroing ----------------
__global__ void k_zeroA() {
    int i = blockIdx.x * blockDim.x + threadIdx.x;   // NN*NN/4 float4s
    ((float4*)g_A)[i] = make_float4(0.f, 0.f, 0.f, 0.f);
}
__global__ void k_zeroA2f() {
    int i = blockIdx.x * blockDim.x + threadIdx.x;   // NN*NN/4 float4s
    ((float4*)g_A2f)[i] = make_float4(0.f, 0.f, 0.f, 0.f);
}
// Small arrays + dtype detection (single block, on s2 ahead of the scatter).
__global__ void k_zeroSmall(const unsigned* __restrict__ w) {
    __shared__ int anynz;
    if (threadIdx.x == 0) anynz = 0;
    __syncthreads();
    unsigned v = 0;
    for (int i = 1 + 2 * threadIdx.x; i < 8192; i += 2 * blockDim.x) v |= w[i];
    if (v) anynz = 1;
    for (int j = threadIdx.x; j < NN; j += 256) {
        g_cur[j] = 0; g_norm2[j] = 0.f;
    }
    if (threadIdx.x < 2 * HH) {
        ((unsigned*)g_hmaxu)[threadIdx.x] = 0u;
        ((float*)g_Zsum)[threadIdx.x] = 0.f;
    }
    __syncthreads();
    if (threadIdx.x == 0) g_is64 = anynz ? 0 : 1;
}

__global__ void k_buildA(const void* __restrict__ ei) {
    int e = blockIdx.x * blockDim.x + threadIdx.x;
    if (e >= EE) return;
    int s = eidx(ei, e), d = eidx(ei, EE + e);
    atomicAdd(&g_A[s * NN + d], 1.0f);
}

// ---------------- bucketed CSR-by-dst (direct append; no count/scan) ----------
__global__ void k_scatter(const void* __restrict__ ei) {
    int e = blockIdx.x * blockDim.x + threadIdx.x;
    if (e >= EE) return;
    int s = eidx(ei, e), d = eidx(ei, EE + e);
    int pos = atomicAdd(&g_cur[d], 1);
    if (pos < DCAP) {
        g_ssrc[d * DCAP + pos] = s;
        g_seid[d * DCAP + pos] = e;
    }
}

// ---------------- sparse A^2: for edge (k->j), +1 for each in-edge (i->k) ----
__global__ void k_buildA2(const void* __restrict__ ei) {
    int e = blockIdx.x * blockDim.x + threadIdx.x;
    if (e >= EE) return;
    int k = eidx(ei, e), j = eidx(ei, EE + e);
    int cnt = g_cur[k];
    if (cnt > DCAP) cnt = DCAP;
    const int base = k * DCAP;
    for (int idx = 0; idx < cnt; idx++) {
        int i = g_ssrc[base + idx];
        atomicAdd(&g_A2f[(size_t)i * NN + j], 1.0f);
    }
}

// ---------------- fused prep: A2' = A2raw + 2A + I ; S = A' + A2' ; R = S + I ;
//                  A2bf = bf16(A2') ; STbf = bf16(S)^T ----------------------------
__global__ void k_prep() {
    __shared__ float tile[32][33];
    const int tx = threadIdx.x, ty = threadIdx.y;
    const int bx = blockIdx.x * 32, by = blockIdx.y * 32;
    #pragma unroll
    for (int r = 0; r < 32; r += 8) {
        int row = by + ty + r, col = bx + tx;
        size_t o = (size_t)row * NN + col;
        float a = g_A[o];
        float b = g_A2f[o];
        float diag = (row == col) ? 1.0f : 0.0f;
        float a2 = b + 2.0f * a + diag;       // A'^2
        float S  = a + a2 + diag;             // A' + A'^2
        g_R[o] = S + diag;                    // I + A' + A'^2
        g_A2bf[o] = __float2bfloat16(a2);
        tile[ty + r][tx] = S;
    }
    __syncthreads();
    #pragma unroll
    for (int r = 0; r < 32; r += 8)
        g_STbf[(size_t)(bx + ty + r) * NN + by + tx] =
            __float2bfloat16(tile[tx][ty + r]);
}

// ================= HMMA bf16 GEMM (mma.sync m16n8k16, cp.async pipeline) =========
#define GKC    64
#define NCHUNK (NN / GKC)
#define SM_TILE 16384
#define GEMM_SMEM (4 * SM_TILE)

__device__ __forceinline__ uint32_t smem_u32(const void* p) {
    uint32_t a;
    asm("{ .reg .u64 t; cvta.to.shared.u64 t, %1; cvt.u32.u64 %0, t; }" : "=r"(a) : "l"(p));
    return a;
}

__device__ __forceinline__ void cp16(uint32_t saddr, const void* gaddr) {
    asm volatile("cp.async.cg.shared.global [%0], [%1], 16;" :: "r"(saddr), "l"(gaddr));
}

__device__ __forceinline__ void ldmx4(uint32_t addr, uint32_t& r0, uint32_t& r1,
                                      uint32_t& r2, uint32_t& r3) {
    asm volatile("ldmatrix.sync.aligned.m8n8.x4.shared.b16 {%0,%1,%2,%3}, [%4];"
                 : "=r"(r0), "=r"(r1), "=r"(r2), "=r"(r3) : "r"(addr));
}

__device__ __forceinline__ void mma16816(float* d, uint32_t a0, uint32_t a1,
                                         uint32_t a2, uint32_t a3,
                                         uint32_t b0, uint32_t b1) {
    asm volatile("mma.sync.aligned.m16n8k16.row.col.f32.bf16.bf16.f32 "
                 "{%0,%1,%2,%3}, {%4,%5,%6,%7}, {%8,%9}, {%0,%1,%2,%3};"
                 : "+f"(d[0]), "+f"(d[1]), "+f"(d[2]), "+f"(d[3])
                 : "r"(a0), "r"(a1), "r"(a2), "r"(a3), "r"(b0), "r"(b1));
}

__global__ __launch_bounds__(256, 2)
void gemm_bf16mma(const __nv_bfloat16* __restrict__ Aop,
                  const __nv_bfloat16* __restrict__ Bop,
                  float* __restrict__ Cout)
{
    extern __shared__ __align__(1024) char smem[];
    const uint32_t sbase = smem_u32(smem);
    const int tid  = threadIdx.x;
    const int lane = tid & 31;
    const int w    = tid >> 5;
    const int wm   = w & 3;
    const int wn   = w >> 2;
    const int bm = blockIdx.y * 128, bn = blockIdx.x * 128;

    const int row0 = tid >> 3, seg = tid & 7;
    const __nv_bfloat16* abase = Aop + (size_t)(bm + row0) * NN + seg * 8;
    const __nv_bfloat16* bbase = Bop + (size_t)(bn + row0) * NN + seg * 8;
    const uint32_t soff0 = row0 * 128 + (((row0 & 7) << 4) ^ (seg * 16));

    const int a_r  = lane & 15;
    const int a_hi = lane >> 4;
    const int a_xor = (a_r & 7) << 4;
    const int arow0 = wm * 32 + a_r;
    const int b_g = lane >> 3, b_w = lane & 7;
    const int b_xor = b_w << 4;
    const int brow_base = wn * 64 + ((b_g >> 1) << 3) + b_w;
    const int b_khi = (b_g & 1) * 16;

    float acc[2][8][4];
    #pragma unroll
    for (int i = 0; i < 2; i++)
        #pragma unroll
        for (int j = 0; j < 8; j++)
            #pragma unroll
            for (int t = 0; t < 4; t++) acc[i][j][t] = 0.f;

    {
        const uint32_t dA = sbase, dB = sbase + 2 * SM_TILE;
        #pragma unroll
        for (int i = 0; i < 4; i++)
            cp16(dA + soff0 + i * 4096, abase + (size_t)(32 * i) * NN);
        #pragma unroll
        for (int i = 0; i < 4; i++)
            cp16(dB + soff0 + i * 4096, bbase + (size_t)(32 * i) * NN);
        asm volatile("cp.async.commit_group;");
    }

    for (int c = 0; c < NCHUNK; c++) {
        asm volatile("cp.async.wait_group 0;");
        __syncthreads();

        if (c + 1 < NCHUNK) {
            const int nb = (c + 1) & 1;
            const uint32_t dA = sbase + nb * SM_TILE;
            const uint32_t dB = sbase + 2 * SM_TILE + nb * SM_TILE;
            const __nv_bfloat16* ap = abase + (c + 1) * GKC;
            const __nv_bfloat16* bp = bbase + (c + 1) * GKC;
            #pragma unroll
            for (int i = 0; i < 4; i++)
                cp16(dA + soff0 + i * 4096, ap + (size_t)(32 * i) * NN);
            #pragma unroll
            for (int i = 0; i < 4; i++)
                cp16(dB + soff0 + i * 4096, bp + (size_t)(32 * i) * NN);
            asm volatile("cp.async.commit_group;");
        }

        const int buf = c & 1;
        const uint32_t sA = sbase + buf * SM_TILE;
        const uint32_t sB = sbase + 2 * SM_TILE + buf * SM_TILE;

        #pragma unroll
        for (int ks = 0; ks < 4; ks++) {
            uint32_t a[2][4];
            #pragma unroll
            for (int im = 0; im < 2; im++) {
                int row = arow0 + im * 16;
                uint32_t addr = sA + row * 128 + (a_xor ^ (ks * 32 + a_hi * 16));
                ldmx4(addr, a[im][0], a[im][1], a[im][2], a[im][3]);
            }
            #pragma unroll
            for (int jn = 0; jn < 4; jn++) {
                int row = brow_base + jn * 16;
                uint32_t addr = sB + row * 128 + (b_xor ^ (ks * 32 + b_khi));
                uint32_t r0, r1, r2, r3;
                ldmx4(addr, r0, r1, r2, r3);
                mma16816(acc[0][2 * jn],     a[0][0], a[0][1], a[0][2], a[0][3], r0, r1);
                mma16816(acc[0][2 * jn + 1], a[0][0], a[0][1], a[0][2], a[0][3], r2, r3);
                mma16816(acc[1][2 * jn],     a[1][0], a[1][1], a[1][2], a[1][3], r0, r1);
                mma16816(acc[1][2 * jn + 1], a[1][0], a[1][1], a[1][2], a[1][3], r2, r3);
            }
        }
    }

    // epilogue: R += acc and accumulate row sums of R^2 (for mask norms)
    const int mrow = bm + wm * 32 + (lane >> 2);
    const int ncol = bn + wn * 64 + 2 * (lane & 3);
    #pragma unroll
    for (int im = 0; im < 2; im++) {
        #pragma unroll
        for (int half = 0; half < 2; half++) {
            int m = mrow + im * 16 + half * 8;
            float ss = 0.f;
            #pragma unroll
            for (int jf = 0; jf < 8; jf++) {
                int n = ncol + jf * 8;
                float2* cp = (float2*)&Cout[(size_t)m * NN + n];
                float2 cv = *cp;
                cv.x += acc[im][jf][2 * half];
                cv.y += acc[im][jf][2 * half + 1];
                *cp = cv;
                ss += cv.x * cv.x + cv.y * cv.y;
            }
            atomicAdd(&g_norm2[m], ss);
        }
    }
}

// ---------------- fp32 SIMT GEMM, 64x128 tiles: C = A*B^T (K=128) ----------------
// MODE 0: C = acc ; MODE 1: C = acc + bias[n]
// ATT: output tile spans exactly one head; also emit si/sj dot products.
template<int MODE, bool ATT>
__global__ __launch_bounds__(256, 4)
void gemm_f32(const float* __restrict__ A, const float* __restrict__ B,
              float* __restrict__ C, const float* __restrict__ bias,
              const float* __restrict__ att, int M, int N, int K)
{
    __shared__ float As[BK][64];
    __shared__ float Bs[BK][128];
    const int tid = threadIdx.x;
    const int bm = blockIdx.y * 64;
    const int bn = blockIdx.x * 128;
    const int arow = tid >> 2, acol = (tid & 3) * 2;
    const int brow = tid >> 1, bcol = (tid & 1) * 4;
    const int ty = tid >> 4;
    const int tx = tid & 15;

    float acc[4][8];
    #pragma unroll
    for (int i = 0; i < 4; i++)
        #pragma unroll
        for (int j = 0; j < 8; j++) acc[i][j] = 0.f;

    for (int k0 = 0; k0 < K; k0 += BK) {
        float2 av = *(const float2*)&A[(size_t)(bm + arow) * K + k0 + acol];
        As[acol][arow] = av.x;
        As[acol + 1][arow] = av.y;
        float4 bv = *(const float4*)&B[(size_t)(bn + brow) * K + k0 + bcol];
        Bs[bcol + 0][brow] = bv.x;
        Bs[bcol + 1][brow] = bv.y;
        Bs[bcol + 2][brow] = bv.z;
        Bs[bcol + 3][brow] = bv.w;
        __syncthreads();

        #pragma unroll
        for (int k = 0; k < BK; k++) {
            float4 a = *(const float4*)&As[k][ty * 4];
            float4 b0 = *(const float4*)&Bs[k][tx * 8];
            float4 b1 = *(const float4*)&Bs[k][tx * 8 + 4];
            float ra[4] = {a.x, a.y, a.z, a.w};
            float rb[8] = {b0.x, b0.y, b0.z, b0.w, b1.x, b1.y, b1.z, b1.w};
            #pragma unroll
            for (int i = 0; i < 4; i++)
                #pragma unroll
                for (int j = 0; j < 8; j++)
                    acc[i][j] += ra[i] * rb[j];
        }
        __syncthreads();
    }

    #pragma unroll
    for (int i = 0; i < 4; i++) {
        int row = bm + ty * 4 + i;
        float* cp = &C[(size_t)row * N + bn + tx * 8];
        if (MODE == 0) {
            *(float4*)&cp[0] = make_float4(acc[i][0], acc[i][1], acc[i][2], acc[i][3]);
            *(float4*)&cp[4] = make_float4(acc[i][4], acc[i][5], acc[i][6], acc[i][7]);
        } else {
            const float* bp = &bias[bn + tx * 8];
            *(float4*)&cp[0] = make_float4(acc[i][0] + bp[0], acc[i][1] + bp[1],
                                           acc[i][2] + bp[2], acc[i][3] + bp[3]);
            *(float4*)&cp[4] = make_float4(acc[i][4] + bp[4], acc[i][5] + bp[5],
                                           acc[i][6] + bp[6], acc[i][7] + bp[7]);
        }
    }

    if (ATT) {
        const int h = blockIdx.x;                  // 128-wide tile == head h
        const float* ai = att + h * (2 * CC) + tx * 8;
        const float* aj = ai + CC;
        float av_i[8], av_j[8];
        #pragma unroll
        for (int j = 0; j < 8; j++) { av_i[j] = ai[j]; av_j[j] = aj[j]; }
        #pragma unroll
        for (int i = 0; i < 4; i++) {
            float pi = 0.f, pj = 0.f;
            #pragma unroll
            for (int j = 0; j < 8; j++) {
                pi += acc[i][j] * av_i[j];
                pj += acc[i][j] * av_j[j];
            }
            #pragma unroll
            for (int o = 8; o > 0; o >>= 1) {
                pi += __shfl_xor_sync(0xffffffffu, pi, o, 16);
                pj += __shfl_xor_sync(0xffffffffu, pj, o, 16);
            }
            if (tx == 0) {
                int row = bm + ty * 4 + i;
                g_si[row * HH + h] = pi;
                g_sj[row * HH + h] = pj;
            }
        }
    }
}

// ---------------- attention ----------------
// z computation + per-head max accumulation. LAYER 0 also computes/caches g_mv.
template<int LAYER>
__global__ void k_z(const void* __restrict__ ei) {
    __shared__ unsigned smax[HH];
    if (threadIdx.x < HH) smax[threadIdx.x] = 0u;
    __syncthreads();
    int e = blockIdx.x * blockDim.x + threadIdx.x;
    int s = eidx(ei, e), d = eidx(ei, EE + e);
    float mv;
    if (LAYER == 0) {
        float nrm = fmaxf(sqrtf(g_norm2[s]), 1e-12f);
        mv = g_R[(size_t)s * NN + d] / nrm;
        g_mv[e] = mv;
    } else {
        mv = g_mv[e];
    }
    float z[HH];
    #pragma unroll
    for (int h = 0; h < HH; h++) {
        float a = g_si[d * HH + h] + g_sj[s * HH + h];
        a = (a >= 0.f) ? a : NEG * a;
        z[h] = a * mv;
    }
    *(float4*)&g_z[(size_t)e * HH]     = make_float4(z[0], z[1], z[2], z[3]);
    *(float4*)&g_z[(size_t)e * HH + 4] = make_float4(z[4], z[5], z[6], z[7]);
    #pragma unroll
    for (int h = 0; h < HH; h++) {
        float m = z[h];
        #pragma unroll
        for (int o = 16; o > 0; o >>= 1)
            m = fmaxf(m, __shfl_xor_sync(0xffffffffu, m, o));
        if ((threadIdx.x & 31) == 0) atomicMax(&smax[h], encf(m));
    }
    __syncthreads();
    if (threadIdx.x < HH) atomicMax(&g_hmaxu[LAYER][threadIdx.x], smax[threadIdx.x]);
}

// exp(z - m_h) in place + per-head sums. One thread per edge (8 floats).
template<int LAYER>
__global__ void k_expsum() {
    __shared__ float ssum[HH];
    if (threadIdx.x < HH) ssum[threadIdx.x] = 0.f;
    __syncthreads();
    int e = blockIdx.x * blockDim.x + threadIdx.x;
    float4 v0 = *(float4*)&g_z[(size_t)e * HH];
    float4 v1 = *(float4*)&g_z[(size_t)e * HH + 4];
    float zv[HH] = {v0.x, v0.y, v0.z, v0.w, v1.x, v1.y, v1.z, v1.w};
    #pragma unroll
    for (int h = 0; h < HH; h++)
        zv[h] = expf(zv[h] - decf(g_hmaxu[LAYER][h]));
    *(float4*)&g_z[(size_t)e * HH]     = make_float4(zv[0], zv[1], zv[2], zv[3]);
    *(float4*)&g_z[(size_t)e * HH + 4] = make_float4(zv[4], zv[5], zv[6], zv[7]);
    #pragma unroll
    for (int h = 0; h < HH; h++) {
        float sm = zv[h];
        #pragma unroll
        for (int o = 16; o > 0; o >>= 1)
            sm += __shfl_xor_sync(0xffffffffu, sm, o);
        if ((threadIdx.x & 31) == 0) atomicAdd(&ssum[h], sm);
    }
    __syncthreads();
    if (threadIdx.x < HH) atomicAdd(&g_Zsum[LAYER][threadIdx.x], ssum[threadIdx.x]);
}

// 256 threads: group 0 handles heads 0-3, group 1 heads 4-7; smem join.
// FINAL: add xskip and write final output.
template<int LAYER, bool FINAL>
__global__ void k_aggregate(float* __restrict__ out) {
    __shared__ float red[128];
    int d = blockIdx.x;
    int c = threadIdx.x & 127;
    int hg = threadIdx.x >> 7;
    int cnt = g_cur[d];
    if (cnt > DCAP) cnt = DCAP;
    const int base = d * DCAP;
    float acc = 0.f;
    #pragma unroll
    for (int hh = 0; hh < 4; hh++) {
        int h = hg * 4 + hh;
        float a = 0.f;
        float invZ = 1.0f / g_Zsum[LAYER][h];
        for (int idx = 0; idx < cnt; idx++) {
            int s = g_ssrc[base + idx];
            int e = g_seid[base + idx];
            a += g_z[(size_t)e * HH + h] * g_xh[(size_t)s * (HH * CC) + h * CC + c];
        }
        acc += a * invZ;
    }
    if (hg == 1) red[c] = acc;
    __syncthreads();
    if (hg == 0) {
        float r = fmaxf((acc + red[c]) * (1.0f / HH), 0.f);
        if (FINAL) r += g_xskip[d * CC + c];
        out[d * CC + c] = r;
    }
}

// ---------------- launch ----------------
extern "C" void kernel_launch(void* const* d_in, const int* in_sizes, int n_in,
                              void* d_out, int out_size) {
    const float* x      = (const float*)d_in[0];
    const void*  ei     = d_in[1];
    const float* lin_w0 = (const float*)d_in[2];
    const float* att0   = (const float*)d_in[3];
    const float* lin_w1 = (const float*)d_in[4];
    const float* att1   = (const float*)d_in[5];
    const float* skip_w = (const float*)d_in[6];
    const float* skip_b = (const float*)d_in[7];
    float* out = (float*)d_out;

    void *pA2bf, *pSTbf;
    float *pR, *pXh, *pH1, *pXs;
    cudaGetSymbolAddress(&pA2bf, g_A2bf);
    cudaGetSymbolAddress(&pSTbf, g_STbf);
    cudaGetSymbolAddress((void**)&pR,  g_R);
    cudaGetSymbolAddress((void**)&pXh, g_xh);
    cudaGetSymbolAddress((void**)&pH1, g_h1);
    cudaGetSymbolAddress((void**)&pXs, g_xskip);

    // One-time resource setup, reused across all calls (no per-call allocation).
    static cudaStream_t s1 = nullptr, s2 = nullptr;
    static cudaEvent_t evRoot = nullptr, evDet = nullptr, evSide = nullptr,
                       evZF = nullptr, evA2 = nullptr;
    static bool init_done = false;
    if (!init_done) {
        cudaFuncSetAttribute(gemm_bf16mma, cudaFuncAttributeMaxDynamicSharedMemorySize, GEMM_SMEM);
        cudaStreamCreateWithFlags(&s1, cudaStreamNonBlocking);
        cudaStreamCreateWithFlags(&s2, cudaStreamNonBlocking);
        cudaEventCreateWithFlags(&evRoot, cudaEventDisableTiming);
        cudaEventCreateWithFlags(&evDet, cudaEventDisableTiming);
        cudaEventCreateWithFlags(&evSide, cudaEventDisableTiming);
        cudaEventCreateWithFlags(&evZF, cudaEventDisableTiming);
        cudaEventCreateWithFlags(&evA2, cudaEventDisableTiming);
        init_done = true;
    }

    // Fork s1/s2 from the origin stream FIRST (graph-capture requirement).
    cudaEventRecord(evRoot, 0);
    cudaStreamWaitEvent(s1, evRoot, 0);
    cudaStreamWaitEvent(s2, evRoot, 0);

    // ---- side track 1 (s1): A2f zero first (slack-filled), then lin/skip ----
    k_zeroA2f<<<(NN * NN / 4) / 256, 256, 0, s1>>>();
    cudaEventRecord(evZF, s1);
    gemm_f32<0, true><<<dim3((HH * CC) / 128, NN / 64), 256, 0, s1>>>(
        x, lin_w0, pXh, nullptr, att0, NN, HH * CC, CC);
    gemm_f32<1, false><<<dim3(CC / 128, NN / 64), 256, 0, s1>>>(
        x, skip_w, pXs, skip_b, nullptr, NN, CC, CC);
    cudaEventRecord(evSide, s1);

    // ---- side track 2 (s2): small zero + detect, bucket scatter, sparse A^2 ----
    k_zeroSmall<<<1, 256, 0, s2>>>((const unsigned*)ei);
    cudaEventRecord(evDet, s2);
    k_scatter<<<EE / 256, 256, 0, s2>>>(ei);
    cudaStreamWaitEvent(s2, evZF, 0);
    k_buildA2<<<EE / 256, 256, 0, s2>>>(ei);
    cudaEventRecord(evA2, s2);

    // ---- main track: A zero, then adjacency (needs is64) ----
    k_zeroA<<<(NN * NN / 4) / 256, 256>>>();
    cudaStreamWaitEvent(0, evDet, 0);
    k_buildA<<<EE / 256, 256>>>(ei);

    // prep + GEMM on main after both builds
    cudaStreamWaitEvent(0, evA2, 0);
    k_prep<<<dim3(NN / 32, NN / 32), dim3(32, 8)>>>();

    dim3 gt(NN / 128, NN / 128);
    gemm_bf16mma<<<gt, 256, GEMM_SMEM>>>((const __nv_bfloat16*)pA2bf,
                                         (const __nv_bfloat16*)pSTbf, pR);

    cudaStreamWaitEvent(0, evSide, 0);

    // ---- layer 1 attention ----
    k_z<0><<<EE / 256, 256>>>(ei);
    k_expsum<0><<<EE / 256, 256>>>();
    k_aggregate<0, false><<<NN, 256>>>(pH1);

    // ---- layer 2 ----
    gemm_f32<0, true><<<dim3((HH * CC) / 128, NN / 64), 256>>>(
        pH1, lin_w1, pXh, nullptr, att1, NN, HH * CC, CC);
    k_z<1><<<EE / 256, 256>>>(ei);
    k_expsum<1><<<EE / 256, 256>>>();
    k_aggregate<1, true><<<NN, 256>>>(out);
}

// round 16
// speedup vs baseline: 1.3556x; 1.3556x over previous
#include <cuda_runtime.h>
#include <cuda_bf16.h>
#include <cstdint>
#include <math.h>

#define NN 2048
#define EE 65536
#define HH 8
#define CC 128
#define NEG 0.2f
#define BK 8

// ---------------- device scratch ----------------
__device__ float          g_A  [NN*NN];    // fp32 raw adjacency counts (NO diag)
__device__ float          g_A2f[NN*NN];    // fp32 A^2 raw (path counts)
__device__ float          g_R  [NN*NN];    // fp32 mask accumulator
__device__ __nv_bfloat16  g_A2bf[NN*NN];   // bf16 A'^2
__device__ __nv_bfloat16  g_STbf[NN*NN];   // (A' + A'^2)^T in bf16
__device__ float g_xh[NN*HH*CC];
__device__ float g_si[NN*HH];
__device__ float g_sj[NN*HH];
__device__ float g_z [EE*HH];              // layout: [e][h]
__device__ float g_mv[EE];
__device__ unsigned g_hmaxu[2][HH];        // encoded per-head maxima, per layer
__device__ float    g_Zsum [2][HH];        // per-head exp sums, per layer
__device__ float g_norm2[NN];
__device__ int   g_cnt[NN];
__device__ int   g_cur[NN];
__device__ int   g_off[NN+1];
__device__ int   g_ssrc[EE];
__device__ int   g_seid[EE];
__device__ float g_h1[NN*CC];
__device__ float g_xskip[NN*CC];
__device__ int   g_is64;

__device__ __forceinline__ int eidx(const void* ei, int pos) {
    if (g_is64) return (int)((const long long*)ei)[pos];
    return ((const int*)ei)[pos];
}

// monotone float<->uint encoding for atomicMax over floats
__device__ __forceinline__ unsigned encf(float f) {
    unsigned b = __float_as_uint(f);
    return (b & 0x80000000u) ? ~b : (b | 0x80000000u);
}
__device__ __forceinline__ float decf(unsigned u) {
    unsigned b = (u & 0x80000000u) ? (u ^ 0x80000000u) : ~u;
    return __uint_as_float(b);
}

// ---------------- dtype detection ----------------
__global__ void k_detect(const unsigned* __restrict__ w) {
    __shared__ int anynz;
    if (threadIdx.x == 0) anynz = 0;
    __syncthreads();
    unsigned v = 0;
    for (int i = 1 + 2 * threadIdx.x; i < 8192; i += 2 * blockDim.x) v |= w[i];
    if (v) anynz = 1;
    __syncthreads();
    if (threadIdx.x == 0) g_is64 = anynz ? 0 : 1;
}

// ---------------- zeroing ----------------
__global__ void k_zero2() {
    int i = blockIdx.x * blockDim.x + threadIdx.x;   // 2*NN*NN/4 float4s
    const int half = (NN * NN) / 4;
    float4 z = make_float4(0.f, 0.f, 0.f, 0.f);
    if (i < half) ((float4*)g_A)[i] = z;
    else          ((float4*)g_A2f)[i - half] = z;
}
__global__ void k_zeroSmall() {
    for (int j = threadIdx.x; j < NN; j += 256) {
        g_cnt[j] = 0; g_cur[j] = 0; g_norm2[j] = 0.f;
    }
    if (threadIdx.x < 2 * HH) {
        ((unsigned*)g_hmaxu)[threadIdx.x] = 0u;
        ((float*)g_Zsum)[threadIdx.x] = 0.f;
    }
}

__global__ void k_buildA(const void* __restrict__ ei) {
    int e = blockIdx.x * blockDim.x + threadIdx.x;
    if (e >= EE) return;
    int s = eidx(ei, e), d = eidx(ei, EE + e);
    atomicAdd(&g_A[s * NN + d], 1.0f);
}

// ---------------- sparse A^2: for edge (k->j), +1 for each in-edge (i->k) ----
__global__ void k_buildA2(const void* __restrict__ ei) {
    int e = blockIdx.x * blockDim.x + threadIdx.x;
    if (e >= EE) return;
    int k = eidx(ei, e), j = eidx(ei, EE + e);
    int s0 = g_off[k], s1 = g_off[k + 1];
    for (int idx = s0; idx < s1; idx++) {
        int i = g_ssrc[idx];
        atomicAdd(&g_A2f[(size_t)i * NN + j], 1.0f);
    }
}

// ---------------- fused prep: A2' = A2raw + 2A + I ; S = A' + A2' ; R = S + I ;
//                  A2bf = bf16(A2') ; STbf = bf16(S)^T ----------------------------
__global__ void k_prep() {
    __shared__ float tile[32][33];
    const int tx = threadIdx.x, ty = threadIdx.y;
    const int bx = blockIdx.x * 32, by = blockIdx.y * 32;
    #pragma unroll
    for (int r = 0; r < 32; r += 8) {
        int row = by + ty + r, col = bx + tx;
        size_t o = (size_t)row * NN + col;
        float a = g_A[o];
        float b = g_A2f[o];
        float diag = (row == col) ? 1.0f : 0.0f;
        float a2 = b + 2.0f * a + diag;       // A'^2
        float S  = a + a2 + diag;             // A' + A'^2
        g_R[o] = S + diag;                    // I + A' + A'^2
        g_A2bf[o] = __float2bfloat16(a2);
        tile[ty + r][tx] = S;
    }
    __syncthreads();
    #pragma unroll
    for (int r = 0; r < 32; r += 8)
        g_STbf[(size_t)(bx + ty + r) * NN + by + tx] =
            __float2bfloat16(tile[tx][ty + r]);
}

// ================= HMMA bf16 GEMM (mma.sync m16n8k16, cp.async pipeline) =========
#define GKC    64
#define NCHUNK (NN / GKC)
#define SM_TILE 16384
#define GEMM_SMEM (4 * SM_TILE)

__device__ __forceinline__ uint32_t smem_u32(const void* p) {
    uint32_t a;
    asm("{ .reg .u64 t; cvta.to.shared.u64 t, %1; cvt.u32.u64 %0, t; }" : "=r"(a) : "l"(p));
    return a;
}

__device__ __forceinline__ void cp16(uint32_t saddr, const void* gaddr) {
    asm volatile("cp.async.cg.shared.global [%0], [%1], 16;" :: "r"(saddr), "l"(gaddr));
}

__device__ __forceinline__ void ldmx4(uint32_t addr, uint32_t& r0, uint32_t& r1,
                                      uint32_t& r2, uint32_t& r3) {
    asm volatile("ldmatrix.sync.aligned.m8n8.x4.shared.b16 {%0,%1,%2,%3}, [%4];"
                 : "=r"(r0), "=r"(r1), "=r"(r2), "=r"(r3) : "r"(addr));
}

__device__ __forceinline__ void mma16816(float* d, uint32_t a0, uint32_t a1,
                                         uint32_t a2, uint32_t a3,
                                         uint32_t b0, uint32_t b1) {
    asm volatile("mma.sync.aligned.m16n8k16.row.col.f32.bf16.bf16.f32 "
                 "{%0,%1,%2,%3}, {%4,%5,%6,%7}, {%8,%9}, {%0,%1,%2,%3};"
                 : "+f"(d[0]), "+f"(d[1]), "+f"(d[2]), "+f"(d[3])
                 : "r"(a0), "r"(a1), "r"(a2), "r"(a3), "r"(b0), "r"(b1));
}

__global__ __launch_bounds__(256, 2)
void gemm_bf16mma(const __nv_bfloat16* __restrict__ Aop,
                  const __nv_bfloat16* __restrict__ Bop,
                  float* __restrict__ Cout)
{
    extern __shared__ __align__(1024) char smem[];
    const uint32_t sbase = smem_u32(smem);
    const int tid  = threadIdx.x;
    const int lane = tid & 31;
    const int w    = tid >> 5;
    const int wm   = w & 3;
    const int wn   = w >> 2;
    const int bm = blockIdx.y * 128, bn = blockIdx.x * 128;

    const int row0 = tid >> 3, seg = tid & 7;
    const __nv_bfloat16* abase = Aop + (size_t)(bm + row0) * NN + seg * 8;
    const __nv_bfloat16* bbase = Bop + (size_t)(bn + row0) * NN + seg * 8;
    const uint32_t soff0 = row0 * 128 + (((row0 & 7) << 4) ^ (seg * 16));

    const int a_r  = lane & 15;
    const int a_hi = lane >> 4;
    const int a_xor = (a_r & 7) << 4;
    const int arow0 = wm * 32 + a_r;
    const int b_g = lane >> 3, b_w = lane & 7;
    const int b_xor = b_w << 4;
    const int brow_base = wn * 64 + ((b_g >> 1) << 3) + b_w;
    const int b_khi = (b_g & 1) * 16;

    float acc[2][8][4];
    #pragma unroll
    for (int i = 0; i < 2; i++)
        #pragma unroll
        for (int j = 0; j < 8; j++)
            #pragma unroll
            for (int t = 0; t < 4; t++) acc[i][j][t] = 0.f;

    {
        const uint32_t dA = sbase, dB = sbase + 2 * SM_TILE;
        #pragma unroll
        for (int i = 0; i < 4; i++)
            cp16(dA + soff0 + i * 4096, abase + (size_t)(32 * i) * NN);
        #pragma unroll
        for (int i = 0; i < 4; i++)
            cp16(dB + soff0 + i * 4096, bbase + (size_t)(32 * i) * NN);
        asm volatile("cp.async.commit_group;");
    }

    for (int c = 0; c < NCHUNK; c++) {
        asm volatile("cp.async.wait_group 0;");
        __syncthreads();

        if (c + 1 < NCHUNK) {
            const int nb = (c + 1) & 1;
            const uint32_t dA = sbase + nb * SM_TILE;
            const uint32_t dB = sbase + 2 * SM_TILE + nb * SM_TILE;
            const __nv_bfloat16* ap = abase + (c + 1) * GKC;
            const __nv_bfloat16* bp = bbase + (c + 1) * GKC;
            #pragma unroll
            for (int i = 0; i < 4; i++)
                cp16(dA + soff0 + i * 4096, ap + (size_t)(32 * i) * NN);
            #pragma unroll
            for (int i = 0; i < 4; i++)
                cp16(dB + soff0 + i * 4096, bp + (size_t)(32 * i) * NN);
            asm volatile("cp.async.commit_group;");
        }

        const int buf = c & 1;
        const uint32_t sA = sbase + buf * SM_TILE;
        const uint32_t sB = sbase + 2 * SM_TILE + buf * SM_TILE;

        #pragma unroll
        for (int ks = 0; ks < 4; ks++) {
            uint32_t a[2][4];
            #pragma unroll
            for (int im = 0; im < 2; im++) {
                int row = arow0 + im * 16;
                uint32_t addr = sA + row * 128 + (a_xor ^ (ks * 32 + a_hi * 16));
                ldmx4(addr, a[im][0], a[im][1], a[im][2], a[im][3]);
            }
            #pragma unroll
            for (int jn = 0; jn < 4; jn++) {
                int row = brow_base + jn * 16;
                uint32_t addr = sB + row * 128 + (b_xor ^ (ks * 32 + b_khi));
                uint32_t r0, r1, r2, r3;
                ldmx4(addr, r0, r1, r2, r3);
                mma16816(acc[0][2 * jn],     a[0][0], a[0][1], a[0][2], a[0][3], r0, r1);
                mma16816(acc[0][2 * jn + 1], a[0][0], a[0][1], a[0][2], a[0][3], r2, r3);
                mma16816(acc[1][2 * jn],     a[1][0], a[1][1], a[1][2], a[1][3], r0, r1);
                mma16816(acc[1][2 * jn + 1], a[1][0], a[1][1], a[1][2], a[1][3], r2, r3);
            }
        }
    }

    // epilogue: R += acc and accumulate row sums of R^2 (for mask norms)
    const int mrow = bm + wm * 32 + (lane >> 2);
    const int ncol = bn + wn * 64 + 2 * (lane & 3);
    #pragma unroll
    for (int im = 0; im < 2; im++) {
        #pragma unroll
        for (int half = 0; half < 2; half++) {
            int m = mrow + im * 16 + half * 8;
            float ss = 0.f;
            #pragma unroll
            for (int jf = 0; jf < 8; jf++) {
                int n = ncol + jf * 8;
                float2* cp = (float2*)&Cout[(size_t)m * NN + n];
                float2 cv = *cp;
                cv.x += acc[im][jf][2 * half];
                cv.y += acc[im][jf][2 * half + 1];
                *cp = cv;
                ss += cv.x * cv.x + cv.y * cv.y;
            }
            atomicAdd(&g_norm2[m], ss);
        }
    }
}

// ---------------- fp32 SIMT GEMM, 64x128 tiles: C = A*B^T (K=128) ----------------
// MODE 0: C = acc ; MODE 1: C = acc + bias[n]
// ATT: output tile spans exactly one head; also emit si/sj dot products.
template<int MODE, bool ATT>
__global__ __launch_bounds__(256, 4)
void gemm_f32(const float* __restrict__ A, const float* __restrict__ B,
              float* __restrict__ C, const float* __restrict__ bias,
              const float* __restrict__ att, int M, int N, int K)
{
    __shared__ float As[BK][64];
    __shared__ float Bs[BK][128];
    const int tid = threadIdx.x;
    const int bm = blockIdx.y * 64;
    const int bn = blockIdx.x * 128;
    const int arow = tid >> 2, acol = (tid & 3) * 2;
    const int brow = tid >> 1, bcol = (tid & 1) * 4;
    const int ty = tid >> 4;
    const int tx = tid & 15;

    float acc[4][8];
    #pragma unroll
    for (int i = 0; i < 4; i++)
        #pragma unroll
        for (int j = 0; j < 8; j++) acc[i][j] = 0.f;

    for (int k0 = 0; k0 < K; k0 += BK) {
        float2 av = *(const float2*)&A[(size_t)(bm + arow) * K + k0 + acol];
        As[acol][arow] = av.x;
        As[acol + 1][arow] = av.y;
        float4 bv = *(const float4*)&B[(size_t)(bn + brow) * K + k0 + bcol];
        Bs[bcol + 0][brow] = bv.x;
        Bs[bcol + 1][brow] = bv.y;
        Bs[bcol + 2][brow] = bv.z;
        Bs[bcol + 3][brow] = bv.w;
        __syncthreads();

        #pragma unroll
        for (int k = 0; k < BK; k++) {
            float4 a = *(const float4*)&As[k][ty * 4];
            float4 b0 = *(const float4*)&Bs[k][tx * 8];
            float4 b1 = *(const float4*)&Bs[k][tx * 8 + 4];
            float ra[4] = {a.x, a.y, a.z, a.w};
            float rb[8] = {b0.x, b0.y, b0.z, b0.w, b1.x, b1.y, b1.z, b1.w};
            #pragma unroll
            for (int i = 0; i < 4; i++)
                #pragma unroll
                for (int j = 0; j < 8; j++)
                    acc[i][j] += ra[i] * rb[j];
        }
        __syncthreads();
    }

    #pragma unroll
    for (int i = 0; i < 4; i++) {
        int row = bm + ty * 4 + i;
        float* cp = &C[(size_t)row * N + bn + tx * 8];
        if (MODE == 0) {
            *(float4*)&cp[0] = make_float4(acc[i][0], acc[i][1], acc[i][2], acc[i][3]);
            *(float4*)&cp[4] = make_float4(acc[i][4], acc[i][5], acc[i][6], acc[i][7]);
        } else {
            const float* bp = &bias[bn + tx * 8];
            *(float4*)&cp[0] = make_float4(acc[i][0] + bp[0], acc[i][1] + bp[1],
                                           acc[i][2] + bp[2], acc[i][3] + bp[3]);
            *(float4*)&cp[4] = make_float4(acc[i][4] + bp[4], acc[i][5] + bp[5],
                                           acc[i][6] + bp[6], acc[i][7] + bp[7]);
        }
    }

    if (ATT) {
        const int h = blockIdx.x;                  // 128-wide tile == head h
        const float* ai = att + h * (2 * CC) + tx * 8;
        const float* aj = ai + CC;
        float av_i[8], av_j[8];
        #pragma unroll
        for (int j = 0; j < 8; j++) { av_i[j] = ai[j]; av_j[j] = aj[j]; }
        #pragma unroll
        for (int i = 0; i < 4; i++) {
            float pi = 0.f, pj = 0.f;
            #pragma unroll
            for (int j = 0; j < 8; j++) {
                pi += acc[i][j] * av_i[j];
                pj += acc[i][j] * av_j[j];
            }
            #pragma unroll
            for (int o = 8; o > 0; o >>= 1) {
                pi += __shfl_xor_sync(0xffffffffu, pi, o, 16);
                pj += __shfl_xor_sync(0xffffffffu, pj, o, 16);
            }
            if (tx == 0) {
                int row = bm + ty * 4 + i;
                g_si[row * HH + h] = pi;
                g_sj[row * HH + h] = pj;
            }
        }
    }
}

// ---------------- CSR by dst ----------------
__global__ void k_count(const void* __restrict__ ei) {
    int e = blockIdx.x * blockDim.x + threadIdx.x;
    if (e >= EE) return;
    atomicAdd(&g_cnt[eidx(ei, EE + e)], 1);
}

__global__ void k_scan() {
    __shared__ int wsum[32];
    const int t = threadIdx.x;
    const int lane = t & 31, wid = t >> 5;
    int a = g_cnt[2 * t], b = g_cnt[2 * t + 1];
    int p = a + b;
    int v = p;
    #pragma unroll
    for (int o = 1; o < 32; o <<= 1) {
        int n = __shfl_up_sync(0xffffffffu, v, o);
        if (lane >= o) v += n;
    }
    if (lane == 31) wsum[wid] = v;
    __syncthreads();
    if (wid == 0) {
        int wv = wsum[lane];
        #pragma unroll
        for (int o = 1; o < 32; o <<= 1) {
            int n = __shfl_up_sync(0xffffffffu, wv, o);
            if (lane >= o) wv += n;
        }
        wsum[lane] = wv;
    }
    __syncthreads();
    int base = (wid > 0 ? wsum[wid - 1] : 0) + (v - p);
    g_off[2 * t]     = base;
    g_off[2 * t + 1] = base + a;
    if (t == 1023) g_off[NN] = base + a + b;
}

__global__ void k_scatter(const void* __restrict__ ei) {
    int e = blockIdx.x * blockDim.x + threadIdx.x;
    if (e >= EE) return;
    int s = eidx(ei, e), d = eidx(ei, EE + e);
    int pos = g_off[d] + atomicAdd(&g_cur[d], 1);
    g_ssrc[pos] = s;
    g_seid[pos] = e;
}

// ---------------- attention ----------------
// z computation + per-head max accumulation. LAYER 0 also computes/caches g_mv.
template<int LAYER>
__global__ void k_z(const void* __restrict__ ei) {
    __shared__ unsigned smax[HH];
    if (threadIdx.x < HH) smax[threadIdx.x] = 0u;
    __syncthreads();
    int e = blockIdx.x * blockDim.x + threadIdx.x;
    int s = eidx(ei, e), d = eidx(ei, EE + e);
    float mv;
    if (LAYER == 0) {
        float nrm = fmaxf(sqrtf(g_norm2[s]), 1e-12f);
        mv = g_R[(size_t)s * NN + d] / nrm;
        g_mv[e] = mv;
    } else {
        mv = g_mv[e];
    }
    float z[HH];
    #pragma unroll
    for (int h = 0; h < HH; h++) {
        float a = g_si[d * HH + h] + g_sj[s * HH + h];
        a = (a >= 0.f) ? a : NEG * a;
        z[h] = a * mv;
    }
    *(float4*)&g_z[(size_t)e * HH]     = make_float4(z[0], z[1], z[2], z[3]);
    *(float4*)&g_z[(size_t)e * HH + 4] = make_float4(z[4], z[5], z[6], z[7]);
    #pragma unroll
    for (int h = 0; h < HH; h++) {
        float m = z[h];
        #pragma unroll
        for (int o = 16; o > 0; o >>= 1)
            m = fmaxf(m, __shfl_xor_sync(0xffffffffu, m, o));
        if ((threadIdx.x & 31) == 0) atomicMax(&smax[h], encf(m));
    }
    __syncthreads();
    if (threadIdx.x < HH) atomicMax(&g_hmaxu[LAYER][threadIdx.x], smax[threadIdx.x]);
}

// exp(z - m_h) in place + per-head sums. One thread per edge (8 floats).
template<int LAYER>
__global__ void k_expsum() {
    __shared__ float ssum[HH];
    if (threadIdx.x < HH) ssum[threadIdx.x] = 0.f;
    __syncthreads();
    int e = blockIdx.x * blockDim.x + threadIdx.x;
    float4 v0 = *(float4*)&g_z[(size_t)e * HH];
    float4 v1 = *(float4*)&g_z[(size_t)e * HH + 4];
    float zv[HH] = {v0.x, v0.y, v0.z, v0.w, v1.x, v1.y, v1.z, v1.w};
    #pragma unroll
    for (int h = 0; h < HH; h++)
        zv[h] = expf(zv[h] - decf(g_hmaxu[LAYER][h]));
    *(float4*)&g_z[(size_t)e * HH]     = make_float4(zv[0], zv[1], zv[2], zv[3]);
    *(float4*)&g_z[(size_t)e * HH + 4] = make_float4(zv[4], zv[5], zv[6], zv[7]);
    #pragma unroll
    for (int h = 0; h < HH; h++) {
        float sm = zv[h];
        #pragma unroll
        for (int o = 16; o > 0; o >>= 1)
            sm += __shfl_xor_sync(0xffffffffu, sm, o);
        if ((threadIdx.x & 31) == 0) atomicAdd(&ssum[h], sm);
    }
    __syncthreads();
    if (threadIdx.x < HH) atomicAdd(&g_Zsum[LAYER][threadIdx.x], ssum[threadIdx.x]);
}

// 256 threads: group 0 handles heads 0-3, group 1 heads 4-7; smem join.
// idx-outer loop: one ssrc/seid load + one float4 z load per edge per thread.
template<int LAYER, bool FINAL>
__global__ void k_aggregate(float* __restrict__ out) {
    __shared__ float red[128];
    int d = blockIdx.x;
    int c = threadIdx.x & 127;
    int hg = threadIdx.x >> 7;
    int s0 = g_off[d], s1 = g_off[d + 1];
    float a0 = 0.f, a1 = 0.f, a2 = 0.f, a3 = 0.f;
    const int hb = hg * 4;
    for (int idx = s0; idx < s1; idx++) {
        int s = g_ssrc[idx];
        int e = g_seid[idx];
        float4 z4 = *(const float4*)&g_z[(size_t)e * HH + hb];
        const float* xr = &g_xh[(size_t)s * (HH * CC) + hb * CC + c];
        a0 += z4.x * xr[0 * CC];
        a1 += z4.y * xr[1 * CC];
        a2 += z4.z * xr[2 * CC];
        a3 += z4.w * xr[3 * CC];
    }
    float acc = a0 / g_Zsum[LAYER][hb + 0]
              + a1 / g_Zsum[LAYER][hb + 1]
              + a2 / g_Zsum[LAYER][hb + 2]
              + a3 / g_Zsum[LAYER][hb + 3];
    if (hg == 1) red[c] = acc;
    __syncthreads();
    if (hg == 0) {
        float r = fmaxf((acc + red[c]) * (1.0f / HH), 0.f);
        if (FINAL) r += g_xskip[d * CC + c];
        out[d * CC + c] = r;
    }
}

// ---------------- launch ----------------
extern "C" void kernel_launch(void* const* d_in, const int* in_sizes, int n_in,
                              void* d_out, int out_size) {
    const float* x      = (const float*)d_in[0];
    const void*  ei     = d_in[1];
    const float* lin_w0 = (const float*)d_in[2];
    const float* att0   = (const float*)d_in[3];
    const float* lin_w1 = (const float*)d_in[4];
    const float* att1   = (const float*)d_in[5];
    const float* skip_w = (const float*)d_in[6];
    const float* skip_b = (const float*)d_in[7];
    float* out = (float*)d_out;

    void *pA2bf, *pSTbf;
    float *pR, *pXh, *pH1, *pXs;
    cudaGetSymbolAddress(&pA2bf, g_A2bf);
    cudaGetSymbolAddress(&pSTbf, g_STbf);
    cudaGetSymbolAddress((void**)&pR,  g_R);
    cudaGetSymbolAddress((void**)&pXh, g_xh);
    cudaGetSymbolAddress((void**)&pH1, g_h1);
    cudaGetSymbolAddress((void**)&pXs, g_xskip);

    // One-time resource setup, reused across all calls (no per-call allocation).
    static cudaStream_t s1 = nullptr, s2 = nullptr;
    static cudaEvent_t ev0 = nullptr, evSide = nullptr, evZ2 = nullptr, evA2 = nullptr;
    static bool init_done = false;
    if (!init_done) {
        cudaFuncSetAttribute(gemm_bf16mma, cudaFuncAttributeMaxDynamicSharedMemorySize, GEMM_SMEM);
        cudaStreamCreateWithFlags(&s1, cudaStreamNonBlocking);
        cudaStreamCreateWithFlags(&s2, cudaStreamNonBlocking);
        cudaEventCreateWithFlags(&ev0, cudaEventDisableTiming);
        cudaEventCreateWithFlags(&evSide, cudaEventDisableTiming);
        cudaEventCreateWithFlags(&evZ2, cudaEventDisableTiming);
        cudaEventCreateWithFlags(&evA2, cudaEventDisableTiming);
        init_done = true;
    }

    k_detect<<<1, 256>>>((const unsigned*)ei);
    cudaEventRecord(ev0, 0);
    cudaStreamWaitEvent(s1, ev0, 0);
    cudaStreamWaitEvent(s2, ev0, 0);

    // ---- side track 1 (s1): layer-1 lin (+fused att scores) + skip ----
    gemm_f32<0, true><<<dim3((HH * CC) / 128, NN / 64), 256, 0, s1>>>(
        x, lin_w0, pXh, nullptr, att0, NN, HH * CC, CC);
    gemm_f32<1, false><<<dim3(CC / 128, NN / 64), 256, 0, s1>>>(
        x, skip_w, pXs, skip_b, nullptr, NN, CC, CC);
    cudaEventRecord(evSide, s1);

    // ---- side track 2 (s2): small zero + CSR chain ----
    k_zeroSmall<<<1, 256, 0, s2>>>();
    k_count<<<EE / 256, 256, 0, s2>>>(ei);
    k_scan<<<1, 1024, 0, s2>>>();
    k_scatter<<<EE / 256, 256, 0, s2>>>(ei);

    // ---- main track: big zero + adjacency ----
    k_zero2<<<(2 * NN * NN / 4) / 256, 256>>>();
    cudaEventRecord(evZ2, 0);
    k_buildA<<<EE / 256, 256>>>(ei);

    // buildA2 on s2 once A2f is zeroed (runs concurrently with buildA)
    cudaStreamWaitEvent(s2, evZ2, 0);
    k_buildA2<<<EE / 256, 256, 0, s2>>>(ei);
    cudaEventRecord(evA2, s2);

    // prep + GEMM on main after both builds
    cudaStreamWaitEvent(0, evA2, 0);
    k_prep<<<dim3(NN / 32, NN / 32), dim3(32, 8)>>>();

    dim3 gt(NN / 128, NN / 128);
    gemm_bf16mma<<<gt, 256, GEMM_SMEM>>>((const __nv_bfloat16*)pA2bf,
                                         (const __nv_bfloat16*)pSTbf, pR);

    cudaStreamWaitEvent(0, evSide, 0);

    // ---- layer 1 attention ----
    k_z<0><<<EE / 256, 256>>>(ei);
    k_expsum<0><<<EE / 256, 256>>>();
    k_aggregate<0, false><<<NN, 256>>>(pH1);

    // ---- layer 2 ----
    gemm_f32<0, true><<<dim3((HH * CC) / 128, NN / 64), 256>>>(
        pH1, lin_w1, pXh, nullptr, att1, NN, HH * CC, CC);
    k_z<1><<<EE / 256, 256>>>(ei);
    k_expsum<1><<<EE / 256, 256>>>();
    k_aggregate<1, true><<<NN, 256>>>(out);
}